// round 4
// baseline (speedup 1.0000x reference)
#include <cuda_runtime.h>

#define V_TOT   131072
#define K_NB    64
#define NSEG    4
#define SEGLEN  (V_TOT / NSEG)     /* 32768 */
#define NBUK    SEGLEN             /* buckets per segment */
#define TOTBUK  (NSEG * NBUK)      /* 131072 */
#define THR     0.5f
#define HALFBUK 16384              /* buckets [0,HALFBUK) <=> score >= 0.5 */
#define QD      8                  /* prefetch queue depth */

/* ---------------- device scratch (no allocations allowed) ---------------- */
__device__ int  g_counts  [TOTBUK];
__device__ int  g_start   [TOTBUK];
__device__ int  g_cursor  [TOTBUK];
__device__ int  g_order   [V_TOT];
__device__ int  g_selLocal[V_TOT];
__device__ int  g_assign  [V_TOT];
__device__ int  g_segCount[NSEG];
__device__ unsigned char g_used[V_TOT];

__device__ __forceinline__ float clip01(float x) { return fminf(fmaxf(x, 0.f), 1.f); }

__device__ __forceinline__ int bucket_of(float sc) {
    int b = (int)(sc * (float)NBUK);
    b = min(b, NBUK - 1);
    return (NBUK - 1) - b;            /* descending score -> ascending bucket */
}

/* ---- init: fill dirn/sel/backgather with -1.0f, reset scratch ---- */
__global__ void k_init(float4* out4, long n4) {
    long i = (long)blockIdx.x * blockDim.x + threadIdx.x;
    long stride = (long)gridDim.x * blockDim.x;
    float4 m1 = make_float4(-1.f, -1.f, -1.f, -1.f);
    for (long j = i; j < n4; j += stride) out4[j] = m1;
    for (long j = i; j < TOTBUK; j += stride) g_counts[j] = 0;
    for (long j = i; j < V_TOT;  j += stride) g_assign[j] = -1;
}

/* ---- bucket histogram ---- */
__global__ void k_count(const float* __restrict__ score) {
    int v = blockIdx.x * blockDim.x + threadIdx.x;
    if (v >= V_TOT) return;
    int s  = v / SEGLEN;
    int bd = bucket_of(clip01(score[v]));
    atomicAdd(&g_counts[s * NBUK + bd], 1);
}

/* ---- exclusive scan over all buckets (Hillis-Steele over 1024 partials) ---- */
__global__ void k_scan() {
    __shared__ int part[1024];
    const int tid   = threadIdx.x;
    const int chunk = TOTBUK / 1024;    /* 128 */
    const int base  = tid * chunk;
    int ssum = 0;
    for (int j = 0; j < chunk; j++) ssum += g_counts[base + j];
    part[tid] = ssum;
    __syncthreads();
    for (int off = 1; off < 1024; off <<= 1) {
        int add = (tid >= off) ? part[tid - off] : 0;
        __syncthreads();
        part[tid] += add;
        __syncthreads();
    }
    int run = part[tid] - ssum;         /* exclusive */
    for (int j = 0; j < chunk; j++) {
        int c = g_counts[base + j];
        g_start [base + j] = run;
        g_cursor[base + j] = run;
        run += c;
    }
}

/* ---- scatter into buckets (intra-bucket order fixed by k_bsort) ---- */
__global__ void k_scatter(const float* __restrict__ score) {
    int v = blockIdx.x * blockDim.x + threadIdx.x;
    if (v >= V_TOT) return;
    int s  = v / SEGLEN;
    int bd = bucket_of(clip01(score[v]));
    int pos = atomicAdd(&g_cursor[s * NBUK + bd], 1);
    g_order[pos] = v;
}

/* ---- exact within-bucket insertion sort: score DESC, index ASC ---- */
__global__ void k_bsort(const float* __restrict__ score) {
    int b = blockIdx.x * blockDim.x + threadIdx.x;
    if (b >= TOTBUK) return;
    int st = g_start[b];
    int en = (b + 1 < TOTBUK) ? g_start[b + 1] : V_TOT;
    if (en - st <= 1) return;
    for (int i = st + 1; i < en; i++) {
        int   key = g_order[i];
        float ks  = clip01(__ldg(&score[key]));
        int j = i - 1;
        while (j >= st) {
            int   oj = g_order[j];
            float os = clip01(__ldg(&score[oj]));
            bool shift = (os < ks) || (os == ks && oj > key);
            if (!shift) break;
            g_order[j + 1] = oj;
            j--;
        }
        g_order[j + 1] = key;
    }
}

/* ======== PHASE A: serial greedy over prefix (score >= 0.5 region) ========
   One warp per segment. Persistent cross-window prefetch queue (depth QD):
   producer scans windows with stale ballots; consumer does the authoritative
   fresh used-check. LDG latency fully hidden by 8-deep lookahead. */
__global__ void __launch_bounds__(32, 1)
k_greedyA(const float* __restrict__ score, const int* __restrict__ nidxs,
          float* __restrict__ out)
{
    extern __shared__ int smem_dyn[];
    int*           sord = smem_dyn;
    unsigned char* used = (unsigned char*)(smem_dyn + SEGLEN);

    const int s       = blockIdx.x;
    const int lane    = threadIdx.x;
    const int segBase = s * SEGLEN;
    const int M       = g_start[s * NBUK + HALFBUK] - g_start[s * NBUK];

    /* stage order (as local ids) + zero used bitmap */
    {
        const int4* src = (const int4*)(g_order + segBase);
        int4*       dst = (int4*)sord;
        for (int i = lane; i < SEGLEN / 4; i += 32) {
            int4 t = src[i];
            t.x -= segBase; t.y -= segBase; t.z -= segBase; t.w -= segBase;
            dst[i] = t;
        }
        int4* u4 = (int4*)used;
        int4  z  = make_int4(0, 0, 0, 0);
        for (int i = lane; i < SEGLEN / 16; i += 32) u4[i] = z;
    }
    __syncwarp();

    float* dirn = out;
    int count = 0;

    /* ---- producer state ---- */
    int      p     = 0;     /* next unscanned window base            */
    int      wbase = 0;     /* window base the mpre bits refer to    */
    unsigned mpre  = 0;     /* stale-unused candidates in wbase win  */
    bool     done  = (M == 0);

    /* ---- prefetch queue (registers) ---- */
    int qv[QD]; float qs[QD]; int qc0[QD], qc1[QD];
    int nq = 0;

    /* push one candidate into slot nq (warp-uniform control) */
#define PUSH_ONE()                                                           \
    {                                                                        \
        for (;;) {                                                           \
            if (mpre) {                                                      \
                int j = __ffs(mpre) - 1; mpre &= mpre - 1;                   \
                int vq = sord[wbase + j];                                    \
                int gv = segBase + vq;                                       \
                qv[nq]  = vq;                                                \
                qs[nq]  = __ldg(score + gv);                                 \
                qc0[nq] = __ldg(nidxs + (size_t)gv * K_NB + lane);           \
                qc1[nq] = __ldg(nidxs + (size_t)gv * K_NB + 32 + lane);      \
                nq++;                                                        \
                break;                                                       \
            }                                                                \
            if (p >= M) { done = true; break; }                              \
            wbase = p;                                                       \
            int idx = p + lane;                                              \
            int vl  = (idx < M) ? sord[idx] : -1;                            \
            mpre = __ballot_sync(0xffffffffu,                                \
                                 (vl >= 0) && (used[vl < 0 ? 0 : vl] == 0)); \
            p += 32;                                                         \
        }                                                                    \
    }

    /* initial fill */
    while (nq < QD && !done) PUSH_ONE();

    while (nq > 0) {
        /* pop head */
        int   vc = qv[0];
        float sc = qs[0];
        int   c0 = qc0[0], c1 = qc1[0];
#pragma unroll
        for (int t = 0; t < QD - 1; t++) {
            qv[t] = qv[t+1]; qs[t] = qs[t+1]; qc0[t] = qc0[t+1]; qc1[t] = qc1[t+1];
        }
        nq--;

        /* refill early so LDGs issue before the critical section */
        while (nq < QD && !done) PUSH_ONE();

        /* fresh pre-state reads (authoritative) */
        unsigned uv = used[vc];
        bool expand = clip01(sc) > THR;
        int l0 = c0 - segBase;
        int l1 = c1 - segBase;
        if (!expand) { l0 = (lane == 0) ? vc : -1; l1 = -1; }
        unsigned u0 = (l0 >= 0) ? used[l0] : 1u;
        unsigned u1 = (l1 >= 0) ? used[l1] : 1u;
        __syncwarp();

        if (uv == 0u) {
            int gv = segBase + vc;
            if (u0 == 0u) {
                used[l0] = 1;
                dirn[(size_t)gv * K_NB + lane] = (float)(segBase + l0);
                g_assign[segBase + l0] = count;
            }
            if (u1 == 0u) {
                used[l1] = 1;
                dirn[(size_t)gv * K_NB + 32 + lane] = (float)(segBase + l1);
                g_assign[segBase + l1] = count;
            }
            if (lane == 0) g_selLocal[segBase + count] = gv;
            count++;
        }
        __syncwarp();
    }
#undef PUSH_ONE

    if (lane == 0) g_segCount[s] = count;

    /* dump used bitmap for phase B */
    {
        int4* src = (int4*)used;
        int4* dst = (int4*)(g_used + segBase);
        for (int i = lane; i < SEGLEN / 16; i += 32) dst[i] = src[i];
    }
}

/* ======== PHASE B: parallel singleton pass over suffix (score < 0.5) ==== */
__global__ void __launch_bounds__(1024)
k_suffix(float* __restrict__ out)
{
    __shared__ int part[1024];
    const int s    = blockIdx.x;
    const int tid  = threadIdx.x;
    const int base = s * SEGLEN;
    const int M      = g_start[s * NBUK + HALFBUK] - base;
    const int countA = g_segCount[s];

    const int N  = SEGLEN - M;
    const int C  = (N + 1023) >> 10;
    const int st = M + tid * C;
    const int en = min(st + C, SEGLEN);

    int cnt = 0;
    for (int i = st; i < en; i++) {
        int v = g_order[base + i];
        cnt += (g_used[v] == 0);
    }
    part[tid] = cnt;
    __syncthreads();
    for (int off = 1; off < 1024; off <<= 1) {
        int add = (tid >= off) ? part[tid - off] : 0;
        __syncthreads();
        part[tid] += add;
        __syncthreads();
    }
    int total = part[1023];
    int rank  = countA + part[tid] - cnt;     /* exclusive */

    for (int i = st; i < en; i++) {
        int v = g_order[base + i];
        if (g_used[v] == 0) {
            out[(size_t)v * K_NB] = (float)v;   /* dirn col 0 = self */
            g_assign[v] = rank;
            g_selLocal[base + rank] = v;
            rank++;
        }
    }
    if (tid == 0) g_segCount[s] = countA + total;
}

/* ---- fixup: global seed-index offsets, sel compaction, rs_new, n_sel ---- */
__global__ void k_fixup(float* __restrict__ out) {
    int c0 = g_segCount[0], c1 = g_segCount[1],
        c2 = g_segCount[2], c3 = g_segCount[3];
    int off1 = c0, off2 = c0 + c1, off3 = c0 + c1 + c2;
    int total = off3 + c3;

    float* sel    = out + (size_t)V_TOT * K_NB;   /* (V,1)  */
    float* assign = sel + V_TOT;                  /* (V,)   */
    float* rs     = assign + V_TOT;               /* (5,)+1 */

    int t      = blockIdx.x * blockDim.x + threadIdx.x;
    int stride = gridDim.x * blockDim.x;

    for (int v = t; v < V_TOT; v += stride) {
        int s = v / SEGLEN;
        int off = (s == 0) ? 0    : (s == 1) ? off1 : (s == 2) ? off2 : off3;
        int cnt = (s == 0) ? c0   : (s == 1) ? c1   : (s == 2) ? c2   : c3;
        int a = g_assign[v];
        if (a >= 0) assign[v] = (float)(a + off);
        int j = v - s * SEGLEN;
        if (j < cnt) sel[off + j] = (float)g_selLocal[v];
    }
    if (t == 0) {
        rs[0] = 0.f;  rs[1] = (float)off1; rs[2] = (float)off2;
        rs[3] = (float)off3; rs[4] = (float)total;
        rs[5] = (float)total;             /* n_sel */
    }
}

/* ------------------------------------------------------------------------ */
extern "C" void kernel_launch(void* const* d_in, const int* in_sizes, int n_in,
                              void* d_out, int out_size)
{
    const float* score = (const float*)d_in[0];
    const int*   nidxs = (const int*)  d_in[1];
    float* out = (float*)d_out;

    const long nfill  = (long)V_TOT * K_NB + 2L * V_TOT;
    const long nfill4 = nfill / 4;

    const int dynBytes = SEGLEN * sizeof(int) + SEGLEN;   /* 128KB + 32KB */
    cudaFuncSetAttribute(k_greedyA,
                         cudaFuncAttributeMaxDynamicSharedMemorySize, dynBytes);

    k_init   <<<2048, 256>>>((float4*)out, nfill4);
    k_count  <<<V_TOT / 256, 256>>>(score);
    k_scan   <<<1, 1024>>>();
    k_scatter<<<V_TOT / 256, 256>>>(score);
    k_bsort  <<<TOTBUK / 256, 256>>>(score);
    k_greedyA<<<NSEG, 32, dynBytes>>>(score, nidxs, out);
    k_suffix <<<NSEG, 1024>>>(out);
    k_fixup  <<<256, 256>>>(out);
}

// round 5
// speedup vs baseline: 1.3652x; 1.3652x over previous
#include <cuda_runtime.h>

#define V_TOT   131072
#define K_NB    64
#define NSEG    4
#define SEGLEN  (V_TOT / NSEG)     /* 32768 */
#define NBUK    SEGLEN             /* buckets per segment */
#define TOTBUK  (NSEG * NBUK)      /* 131072 */
#define THR     0.5f
#define HALFBUK 16384              /* buckets [0,HALFBUK) <=> score >= 0.5 */
#define QD      8                  /* prefetch queue depth */

/* ---------------- device scratch (no allocations allowed) ---------------- */
__device__ int  g_counts  [TOTBUK];
__device__ int  g_start   [TOTBUK];
__device__ int  g_cursor  [TOTBUK];
__device__ int  g_order   [V_TOT];
__device__ int  g_selLocal[V_TOT];
__device__ int  g_assign  [V_TOT];
__device__ int  g_segCount[NSEG];
__device__ unsigned char g_used[V_TOT];

__device__ __forceinline__ float clip01(float x) { return fminf(fmaxf(x, 0.f), 1.f); }

__device__ __forceinline__ int bucket_of(float sc) {
    int b = (int)(sc * (float)NBUK);
    b = min(b, NBUK - 1);
    return (NBUK - 1) - b;            /* descending score -> ascending bucket */
}

/* ---- init: fill dirn/sel/backgather with -1.0f, reset scratch ---- */
__global__ void k_init(float4* out4, long n4) {
    long i = (long)blockIdx.x * blockDim.x + threadIdx.x;
    long stride = (long)gridDim.x * blockDim.x;
    float4 m1 = make_float4(-1.f, -1.f, -1.f, -1.f);
    for (long j = i; j < n4; j += stride) out4[j] = m1;
    for (long j = i; j < TOTBUK; j += stride) g_counts[j] = 0;
    for (long j = i; j < V_TOT;  j += stride) g_assign[j] = -1;
}

/* ---- bucket histogram ---- */
__global__ void k_count(const float* __restrict__ score) {
    int v = blockIdx.x * blockDim.x + threadIdx.x;
    if (v >= V_TOT) return;
    int s  = v / SEGLEN;
    int bd = bucket_of(clip01(score[v]));
    atomicAdd(&g_counts[s * NBUK + bd], 1);
}

/* ---- exclusive scan over all buckets (Hillis-Steele over 1024 partials) ---- */
__global__ void k_scan() {
    __shared__ int part[1024];
    const int tid   = threadIdx.x;
    const int chunk = TOTBUK / 1024;    /* 128 */
    const int base  = tid * chunk;
    int ssum = 0;
    for (int j = 0; j < chunk; j++) ssum += g_counts[base + j];
    part[tid] = ssum;
    __syncthreads();
    for (int off = 1; off < 1024; off <<= 1) {
        int add = (tid >= off) ? part[tid - off] : 0;
        __syncthreads();
        part[tid] += add;
        __syncthreads();
    }
    int run = part[tid] - ssum;         /* exclusive */
    for (int j = 0; j < chunk; j++) {
        int c = g_counts[base + j];
        g_start [base + j] = run;
        g_cursor[base + j] = run;
        run += c;
    }
}

/* ---- scatter into buckets (intra-bucket order fixed by k_bsort) ---- */
__global__ void k_scatter(const float* __restrict__ score) {
    int v = blockIdx.x * blockDim.x + threadIdx.x;
    if (v >= V_TOT) return;
    int s  = v / SEGLEN;
    int bd = bucket_of(clip01(score[v]));
    int pos = atomicAdd(&g_cursor[s * NBUK + bd], 1);
    g_order[pos] = v;
}

/* ---- exact within-bucket insertion sort: score DESC, index ASC ---- */
__global__ void k_bsort(const float* __restrict__ score) {
    int b = blockIdx.x * blockDim.x + threadIdx.x;
    if (b >= TOTBUK) return;
    int st = g_start[b];
    int en = (b + 1 < TOTBUK) ? g_start[b + 1] : V_TOT;
    if (en - st <= 1) return;
    for (int i = st + 1; i < en; i++) {
        int   key = g_order[i];
        float ks  = clip01(__ldg(&score[key]));
        int j = i - 1;
        while (j >= st) {
            int   oj = g_order[j];
            float os = clip01(__ldg(&score[oj]));
            bool shift = (os < ks) || (os == ks && oj > key);
            if (!shift) break;
            g_order[j + 1] = oj;
            j--;
        }
        g_order[j + 1] = key;
    }
}

/* ======== PHASE A: serial greedy over prefix (score >= 0.5 region) ========
   One warp per segment. Persistent cross-window producer + register-resident
   depth-8 prefetch queue (ALL indices compile-time constants -> no local mem).
   Producer ballots are stale heuristics; fresh used[] check is authoritative. */
__global__ void __launch_bounds__(32, 1)
k_greedyA(const float* __restrict__ score, const int* __restrict__ nidxs,
          float* __restrict__ out)
{
    extern __shared__ int smem_dyn[];
    int*           sord = smem_dyn;
    unsigned char* used = (unsigned char*)(smem_dyn + SEGLEN);

    const int s       = blockIdx.x;
    const int lane    = threadIdx.x;
    const int segBase = s * SEGLEN;
    const int M       = g_start[s * NBUK + HALFBUK] - g_start[s * NBUK];

    /* stage order (as local ids) + zero used bitmap */
    {
        const int4* src = (const int4*)(g_order + segBase);
        int4*       dst = (int4*)sord;
        for (int i = lane; i < SEGLEN / 4; i += 32) {
            int4 t = src[i];
            t.x -= segBase; t.y -= segBase; t.z -= segBase; t.w -= segBase;
            dst[i] = t;
        }
        int4* u4 = (int4*)used;
        int4  z  = make_int4(0, 0, 0, 0);
        for (int i = lane; i < SEGLEN / 16; i += 32) u4[i] = z;
    }
    __syncwarp();

    float* dirn = out;
    int count = 0;

    /* ---- producer state (warp-uniform) ---- */
    int      p     = 0;     /* next unscanned window base           */
    int      wbase = 0;     /* window the mpre bits refer to        */
    unsigned mpre  = 0;     /* stale-unused candidates in wbase win */

    /* ---- prefetch queue: constant-indexed register arrays ---- */
    int qv[QD]; float qs[QD]; int qc0[QD], qc1[QD];

    /* produce next candidate into slot T (T is a compile-time constant) */
#define PUSH_SLOT(T)                                                          \
    {                                                                         \
        int vq = -1;                                                          \
        for (;;) {                                                            \
            if (mpre) {                                                       \
                int j = __ffs(mpre) - 1; mpre &= mpre - 1;                    \
                vq = sord[wbase + j];                                         \
                break;                                                        \
            }                                                                 \
            if (p >= M) break;                                                \
            wbase = p;                                                        \
            int idx = p + lane;                                               \
            int vl  = (idx < M) ? sord[idx] : 0;                              \
            mpre = __ballot_sync(0xffffffffu,                                 \
                                 (idx < M) && (used[vl] == 0));               \
            p += 32;                                                          \
        }                                                                     \
        qv[T] = vq;                                                           \
        if (vq >= 0) {                                                        \
            int gv = segBase + vq;                                            \
            qs[T]  = __ldg(score + gv);                                       \
            qc0[T] = __ldg(nidxs + (size_t)gv * K_NB + lane);                 \
            qc1[T] = __ldg(nidxs + (size_t)gv * K_NB + 32 + lane);            \
        }                                                                     \
    }

    /* initial fill: explicit constant slots */
    PUSH_SLOT(0) PUSH_SLOT(1) PUSH_SLOT(2) PUSH_SLOT(3)
    PUSH_SLOT(4) PUSH_SLOT(5) PUSH_SLOT(6) PUSH_SLOT(7)

    while (qv[0] >= 0) {
        /* pop head (constant index) */
        int   vc = qv[0];
        float sc = qs[0];
        int   c0 = qc0[0], c1 = qc1[0];
        /* unrolled shift (constant indices) */
#pragma unroll
        for (int t = 0; t < QD - 1; t++) {
            qv[t] = qv[t+1]; qs[t] = qs[t+1]; qc0[t] = qc0[t+1]; qc1[t] = qc1[t+1];
        }
        /* refill tail early so its LDGs issue before the critical section */
        PUSH_SLOT(QD - 1)

        /* fresh pre-state reads (authoritative) */
        unsigned uv = used[vc];
        bool expand = clip01(sc) > THR;
        int l0 = c0 - segBase;
        int l1 = c1 - segBase;
        if (!expand) { l0 = (lane == 0) ? vc : -1; l1 = -1; }
        unsigned u0 = (l0 >= 0) ? used[l0] : 1u;
        unsigned u1 = (l1 >= 0) ? used[l1] : 1u;
        __syncwarp();

        if (uv == 0u) {
            int gv = segBase + vc;
            if (u0 == 0u) {
                used[l0] = 1;
                dirn[(size_t)gv * K_NB + lane] = (float)(segBase + l0);
                g_assign[segBase + l0] = count;
            }
            if (u1 == 0u) {
                used[l1] = 1;
                dirn[(size_t)gv * K_NB + 32 + lane] = (float)(segBase + l1);
                g_assign[segBase + l1] = count;
            }
            if (lane == 0) g_selLocal[segBase + count] = gv;
            count++;
        }
        __syncwarp();
    }
#undef PUSH_SLOT

    if (lane == 0) g_segCount[s] = count;

    /* dump used bitmap for phase B */
    {
        int4* src = (int4*)used;
        int4* dst = (int4*)(g_used + segBase);
        for (int i = lane; i < SEGLEN / 16; i += 32) dst[i] = src[i];
    }
}

/* ======== PHASE B: parallel singleton pass over suffix (score < 0.5) ==== */
__global__ void __launch_bounds__(1024)
k_suffix(float* __restrict__ out)
{
    __shared__ int part[1024];
    const int s    = blockIdx.x;
    const int tid  = threadIdx.x;
    const int base = s * SEGLEN;
    const int M      = g_start[s * NBUK + HALFBUK] - base;
    const int countA = g_segCount[s];

    const int N  = SEGLEN - M;
    const int C  = (N + 1023) >> 10;
    const int st = M + tid * C;
    const int en = min(st + C, SEGLEN);

    int cnt = 0;
    for (int i = st; i < en; i++) {
        int v = g_order[base + i];
        cnt += (g_used[v] == 0);
    }
    part[tid] = cnt;
    __syncthreads();
    for (int off = 1; off < 1024; off <<= 1) {
        int add = (tid >= off) ? part[tid - off] : 0;
        __syncthreads();
        part[tid] += add;
        __syncthreads();
    }
    int total = part[1023];
    int rank  = countA + part[tid] - cnt;     /* exclusive */

    for (int i = st; i < en; i++) {
        int v = g_order[base + i];
        if (g_used[v] == 0) {
            out[(size_t)v * K_NB] = (float)v;   /* dirn col 0 = self */
            g_assign[v] = rank;
            g_selLocal[base + rank] = v;
            rank++;
        }
    }
    if (tid == 0) g_segCount[s] = countA + total;
}

/* ---- fixup: global seed-index offsets, sel compaction, rs_new, n_sel ---- */
__global__ void k_fixup(float* __restrict__ out) {
    int c0 = g_segCount[0], c1 = g_segCount[1],
        c2 = g_segCount[2], c3 = g_segCount[3];
    int off1 = c0, off2 = c0 + c1, off3 = c0 + c1 + c2;
    int total = off3 + c3;

    float* sel    = out + (size_t)V_TOT * K_NB;   /* (V,1)  */
    float* assign = sel + V_TOT;                  /* (V,)   */
    float* rs     = assign + V_TOT;               /* (5,)+1 */

    int t      = blockIdx.x * blockDim.x + threadIdx.x;
    int stride = gridDim.x * blockDim.x;

    for (int v = t; v < V_TOT; v += stride) {
        int s = v / SEGLEN;
        int off = (s == 0) ? 0    : (s == 1) ? off1 : (s == 2) ? off2 : off3;
        int cnt = (s == 0) ? c0   : (s == 1) ? c1   : (s == 2) ? c2   : c3;
        int a = g_assign[v];
        if (a >= 0) assign[v] = (float)(a + off);
        int j = v - s * SEGLEN;
        if (j < cnt) sel[off + j] = (float)g_selLocal[v];
    }
    if (t == 0) {
        rs[0] = 0.f;  rs[1] = (float)off1; rs[2] = (float)off2;
        rs[3] = (float)off3; rs[4] = (float)total;
        rs[5] = (float)total;             /* n_sel */
    }
}

/* ------------------------------------------------------------------------ */
extern "C" void kernel_launch(void* const* d_in, const int* in_sizes, int n_in,
                              void* d_out, int out_size)
{
    const float* score = (const float*)d_in[0];
    const int*   nidxs = (const int*)  d_in[1];
    float* out = (float*)d_out;

    const long nfill  = (long)V_TOT * K_NB + 2L * V_TOT;
    const long nfill4 = nfill / 4;

    const int dynBytes = SEGLEN * sizeof(int) + SEGLEN;   /* 128KB + 32KB */
    cudaFuncSetAttribute(k_greedyA,
                         cudaFuncAttributeMaxDynamicSharedMemorySize, dynBytes);

    k_init   <<<2048, 256>>>((float4*)out, nfill4);
    k_count  <<<V_TOT / 256, 256>>>(score);
    k_scan   <<<1, 1024>>>();
    k_scatter<<<V_TOT / 256, 256>>>(score);
    k_bsort  <<<TOTBUK / 256, 256>>>(score);
    k_greedyA<<<NSEG, 32, dynBytes>>>(score, nidxs, out);
    k_suffix <<<NSEG, 1024>>>(out);
    k_fixup  <<<256, 256>>>(out);
}

// round 6
// speedup vs baseline: 1.7073x; 1.2506x over previous
#include <cuda_runtime.h>

#define V_TOT   131072
#define K_NB    64
#define NSEG    4
#define SEGLEN  (V_TOT / NSEG)     /* 32768 */
#define NBUK    SEGLEN             /* buckets per segment */
#define TOTBUK  (NSEG * NBUK)      /* 131072 */
#define THR     0.5f
#define HALFBUK 16384              /* buckets [0,HALFBUK) <=> score >= 0.5 */
#define QD      8                  /* prefetch queue depth */

/* ---------------- device scratch (no allocations allowed) ---------------- */
__device__ int  g_counts  [TOTBUK];
__device__ int  g_start   [TOTBUK];
__device__ int  g_cursor  [TOTBUK];
__device__ int  g_order   [V_TOT];
__device__ int  g_selLocal[V_TOT];
__device__ int  g_assign  [V_TOT];
__device__ int  g_segCount[NSEG];
__device__ unsigned char g_used[V_TOT];
/* dummy sinks for predication-by-address (per segment x per lane) */
__device__ float g_dummyF[NSEG * 64];
__device__ int   g_dummyI[NSEG * 64];

__device__ __forceinline__ float clip01(float x) { return fminf(fmaxf(x, 0.f), 1.f); }

__device__ __forceinline__ int bucket_of(float sc) {
    int b = (int)(sc * (float)NBUK);
    b = min(b, NBUK - 1);
    return (NBUK - 1) - b;            /* descending score -> ascending bucket */
}

/* ---- init: fill dirn/sel/backgather with -1.0f, reset scratch ---- */
__global__ void k_init(float4* out4, long n4) {
    long i = (long)blockIdx.x * blockDim.x + threadIdx.x;
    long stride = (long)gridDim.x * blockDim.x;
    float4 m1 = make_float4(-1.f, -1.f, -1.f, -1.f);
    for (long j = i; j < n4; j += stride) out4[j] = m1;
    for (long j = i; j < TOTBUK; j += stride) g_counts[j] = 0;
    for (long j = i; j < V_TOT;  j += stride) g_assign[j] = -1;
}

/* ---- bucket histogram ---- */
__global__ void k_count(const float* __restrict__ score) {
    int v = blockIdx.x * blockDim.x + threadIdx.x;
    if (v >= V_TOT) return;
    int s  = v / SEGLEN;
    int bd = bucket_of(clip01(score[v]));
    atomicAdd(&g_counts[s * NBUK + bd], 1);
}

/* ---- exclusive scan over all buckets (Hillis-Steele over 1024 partials) ---- */
__global__ void k_scan() {
    __shared__ int part[1024];
    const int tid   = threadIdx.x;
    const int chunk = TOTBUK / 1024;    /* 128 */
    const int base  = tid * chunk;
    int ssum = 0;
    for (int j = 0; j < chunk; j++) ssum += g_counts[base + j];
    part[tid] = ssum;
    __syncthreads();
    for (int off = 1; off < 1024; off <<= 1) {
        int add = (tid >= off) ? part[tid - off] : 0;
        __syncthreads();
        part[tid] += add;
        __syncthreads();
    }
    int run = part[tid] - ssum;         /* exclusive */
    for (int j = 0; j < chunk; j++) {
        int c = g_counts[base + j];
        g_start [base + j] = run;
        g_cursor[base + j] = run;
        run += c;
    }
}

/* ---- scatter into buckets (intra-bucket order fixed by k_bsort) ---- */
__global__ void k_scatter(const float* __restrict__ score) {
    int v = blockIdx.x * blockDim.x + threadIdx.x;
    if (v >= V_TOT) return;
    int s  = v / SEGLEN;
    int bd = bucket_of(clip01(score[v]));
    int pos = atomicAdd(&g_cursor[s * NBUK + bd], 1);
    g_order[pos] = v;
}

/* ---- exact within-bucket insertion sort: score DESC, index ASC ---- */
__global__ void k_bsort(const float* __restrict__ score) {
    int b = blockIdx.x * blockDim.x + threadIdx.x;
    if (b >= TOTBUK) return;
    int st = g_start[b];
    int en = (b + 1 < TOTBUK) ? g_start[b + 1] : V_TOT;
    if (en - st <= 1) return;
    for (int i = st + 1; i < en; i++) {
        int   key = g_order[i];
        float ks  = clip01(__ldg(&score[key]));
        int j = i - 1;
        while (j >= st) {
            int   oj = g_order[j];
            float os = clip01(__ldg(&score[oj]));
            bool shift = (os < ks) || (os == ks && oj > key);
            if (!shift) break;
            g_order[j + 1] = oj;
            j--;
        }
        g_order[j + 1] = key;
    }
}

/* ======== PHASE A: serial greedy over prefix (score >= 0.5 region) ========
   One warp per segment. Branch-free consumer: every conditional write is an
   unconditional store to a selected (real-or-dummy) address, so the hot loop
   carries NO BSSY/BSYNC. Queue is shift-free: unroll x QD, static slot ids. */
__global__ void __launch_bounds__(32, 1)
k_greedyA(const float* __restrict__ score, const int* __restrict__ nidxs,
          float* __restrict__ out)
{
    extern __shared__ int smem_dyn[];
    int*           sord = smem_dyn;
    unsigned char* used = (unsigned char*)(smem_dyn + SEGLEN); /* SEGLEN+64 */

    const int s       = blockIdx.x;
    const int lane    = threadIdx.x;
    const int segBase = s * SEGLEN;
    const int M       = g_start[s * NBUK + HALFBUK] - g_start[s * NBUK];
    const int DUMMY   = SEGLEN + lane;           /* per-lane dummy used slot */

    /* stage order (as local ids); zero used bitmap; dummy slots = 1 */
    {
        const int4* src = (const int4*)(g_order + segBase);
        int4*       dst = (int4*)sord;
        for (int i = lane; i < SEGLEN / 4; i += 32) {
            int4 t = src[i];
            t.x -= segBase; t.y -= segBase; t.z -= segBase; t.w -= segBase;
            dst[i] = t;
        }
        int4* u4 = (int4*)used;
        int4  z  = make_int4(0, 0, 0, 0);
        for (int i = lane; i < SEGLEN / 16; i += 32) u4[i] = z;
        used[DUMMY] = 1;
    }
    __syncwarp();

    float* dirn    = out;
    float* dummyF  = g_dummyF + s * 64;
    int*   dummyI  = g_dummyI + s * 64;
    int count = 0;

    /* ---- producer state (warp-uniform) ---- */
    int      p     = 0;
    int      wbase = 0;
    unsigned mpre  = 0;

    /* ---- queue: static-indexed register arrays ---- */
    int qv[QD]; float qs[QD]; int qc0[QD], qc1[QD];

#define PUSH_SLOT(T)                                                          \
    {                                                                         \
        while (mpre == 0u && p < M) {          /* warp-uniform loop */        \
            wbase = p;                                                        \
            int idx = p + lane;                                               \
            int vl  = (idx < M) ? sord[idx] : 0;                              \
            mpre = __ballot_sync(0xffffffffu,                                 \
                                 (idx < M) && (used[vl] == 0));               \
            p += 32;                                                          \
        }                                                                     \
        int j  = __ffs(mpre | 0x80000000u) - 1;  /* j=31 harmless if empty */ \
        int vq = (mpre != 0u) ? sord[wbase + j] : -1;                         \
        mpre &= mpre - 1;                                                     \
        qv[T] = vq;                                                           \
        int gv = segBase + ((vq >= 0) ? vq : 0);  /* clamped, always load */  \
        qs[T]  = __ldg(score + gv);                                           \
        qc0[T] = __ldg(nidxs + (size_t)gv * K_NB + lane);                     \
        qc1[T] = __ldg(nidxs + (size_t)gv * K_NB + 32 + lane);                \
    }

    /* branch-free consumer of slot T; sets 'alive' false on sentinel */
#define POP_SLOT(T)                                                           \
    {                                                                         \
        int vc = qv[T];                                                       \
        if (vc < 0) { alive = false; }                                        \
        else {                                                                \
            float sc = qs[T];                                                 \
            bool expand = sc > THR;                                           \
            int l0 = expand ? (qc0[T] - segBase) : ((lane == 0) ? vc : DUMMY);\
            int l1 = expand ? (qc1[T] - segBase) : DUMMY;                     \
            unsigned uv = used[vc];                                           \
            unsigned u0 = used[l0];                                           \
            unsigned u1 = used[l1];                                           \
            __syncwarp();                                                     \
            bool isNew = (uv == 0u);                                          \
            bool v0 = isNew && (u0 == 0u);                                    \
            bool v1 = isNew && (u1 == 0u);                                    \
            int gv = segBase + vc;                                            \
            used[v0 ? l0 : DUMMY] = 1;                                        \
            used[v1 ? l1 : DUMMY] = 1;                                        \
            float* a0 = v0 ? (dirn + (size_t)gv * K_NB + lane)      : (dummyF + lane);      \
            float* a1 = v1 ? (dirn + (size_t)gv * K_NB + 32 + lane) : (dummyF + 32 + lane); \
            *a0 = (float)(segBase + l0);                                      \
            *a1 = (float)(segBase + l1);                                      \
            int* b0 = v0 ? (g_assign + segBase + l0) : (dummyI + lane);       \
            int* b1 = v1 ? (g_assign + segBase + l1) : (dummyI + 32 + lane);  \
            *b0 = count;                                                      \
            *b1 = count;                                                      \
            int* c = (isNew && lane == 0) ? (g_selLocal + segBase + count)    \
                                          : (dummyI + lane);                  \
            *c = gv;                                                          \
            count += isNew ? 1 : 0;                                           \
            __syncwarp();                                                     \
            PUSH_SLOT(T)                                                      \
        }                                                                     \
    }

    /* initial fill */
    PUSH_SLOT(0) PUSH_SLOT(1) PUSH_SLOT(2) PUSH_SLOT(3)
    PUSH_SLOT(4) PUSH_SLOT(5) PUSH_SLOT(6) PUSH_SLOT(7)

    bool alive = true;
    while (alive) {
        POP_SLOT(0) if (!alive) break;
        POP_SLOT(1) if (!alive) break;
        POP_SLOT(2) if (!alive) break;
        POP_SLOT(3) if (!alive) break;
        POP_SLOT(4) if (!alive) break;
        POP_SLOT(5) if (!alive) break;
        POP_SLOT(6) if (!alive) break;
        POP_SLOT(7)
    }
#undef POP_SLOT
#undef PUSH_SLOT

    if (lane == 0) g_segCount[s] = count;

    /* dump used bitmap for phase B */
    {
        int4* src = (int4*)used;
        int4* dst = (int4*)(g_used + segBase);
        for (int i = lane; i < SEGLEN / 16; i += 32) dst[i] = src[i];
    }
}

/* ======== PHASE B: parallel singleton pass over suffix (score < 0.5) ==== */
__global__ void __launch_bounds__(1024)
k_suffix(float* __restrict__ out)
{
    __shared__ int part[1024];
    const int s    = blockIdx.x;
    const int tid  = threadIdx.x;
    const int base = s * SEGLEN;
    const int M      = g_start[s * NBUK + HALFBUK] - base;
    const int countA = g_segCount[s];

    const int N  = SEGLEN - M;
    const int C  = (N + 1023) >> 10;
    const int st = M + tid * C;
    const int en = min(st + C, SEGLEN);

    int cnt = 0;
    for (int i = st; i < en; i++) {
        int v = g_order[base + i];
        cnt += (g_used[v] == 0);
    }
    part[tid] = cnt;
    __syncthreads();
    for (int off = 1; off < 1024; off <<= 1) {
        int add = (tid >= off) ? part[tid - off] : 0;
        __syncthreads();
        part[tid] += add;
        __syncthreads();
    }
    int total = part[1023];
    int rank  = countA + part[tid] - cnt;     /* exclusive */

    for (int i = st; i < en; i++) {
        int v = g_order[base + i];
        if (g_used[v] == 0) {
            out[(size_t)v * K_NB] = (float)v;   /* dirn col 0 = self */
            g_assign[v] = rank;
            g_selLocal[base + rank] = v;
            rank++;
        }
    }
    if (tid == 0) g_segCount[s] = countA + total;
}

/* ---- fixup: global seed-index offsets, sel compaction, rs_new, n_sel ---- */
__global__ void k_fixup(float* __restrict__ out) {
    int c0 = g_segCount[0], c1 = g_segCount[1],
        c2 = g_segCount[2], c3 = g_segCount[3];
    int off1 = c0, off2 = c0 + c1, off3 = c0 + c1 + c2;
    int total = off3 + c3;

    float* sel    = out + (size_t)V_TOT * K_NB;   /* (V,1)  */
    float* assign = sel + V_TOT;                  /* (V,)   */
    float* rs     = assign + V_TOT;               /* (5,)+1 */

    int t      = blockIdx.x * blockDim.x + threadIdx.x;
    int stride = gridDim.x * blockDim.x;

    for (int v = t; v < V_TOT; v += stride) {
        int s = v / SEGLEN;
        int off = (s == 0) ? 0    : (s == 1) ? off1 : (s == 2) ? off2 : off3;
        int cnt = (s == 0) ? c0   : (s == 1) ? c1   : (s == 2) ? c2   : c3;
        int a = g_assign[v];
        if (a >= 0) assign[v] = (float)(a + off);
        int j = v - s * SEGLEN;
        if (j < cnt) sel[off + j] = (float)g_selLocal[v];
    }
    if (t == 0) {
        rs[0] = 0.f;  rs[1] = (float)off1; rs[2] = (float)off2;
        rs[3] = (float)off3; rs[4] = (float)total;
        rs[5] = (float)total;             /* n_sel */
    }
}

/* ------------------------------------------------------------------------ */
extern "C" void kernel_launch(void* const* d_in, const int* in_sizes, int n_in,
                              void* d_out, int out_size)
{
    const float* score = (const float*)d_in[0];
    const int*   nidxs = (const int*)  d_in[1];
    float* out = (float*)d_out;

    const long nfill  = (long)V_TOT * K_NB + 2L * V_TOT;
    const long nfill4 = nfill / 4;

    const int dynBytes = SEGLEN * sizeof(int) + SEGLEN + 64;  /* sord+used+dummy */
    cudaFuncSetAttribute(k_greedyA,
                         cudaFuncAttributeMaxDynamicSharedMemorySize, dynBytes);

    k_init   <<<2048, 256>>>((float4*)out, nfill4);
    k_count  <<<V_TOT / 256, 256>>>(score);
    k_scan   <<<1, 1024>>>();
    k_scatter<<<V_TOT / 256, 256>>>(score);
    k_bsort  <<<TOTBUK / 256, 256>>>(score);
    k_greedyA<<<NSEG, 32, dynBytes>>>(score, nidxs, out);
    k_suffix <<<NSEG, 1024>>>(out);
    k_fixup  <<<256, 256>>>(out);
}

// round 7
// speedup vs baseline: 1.9739x; 1.1562x over previous
#include <cuda_runtime.h>

#define V_TOT   131072
#define K_NB    64
#define NSEG    4
#define SEGLEN  (V_TOT / NSEG)     /* 32768 */
#define NBUK    SEGLEN             /* buckets per segment */
#define TOTBUK  (NSEG * NBUK)      /* 131072 */
#define THR     0.5f
#define HALFBUK 16384              /* buckets [0,HALFBUK) <=> score >= 0.5 */
#define UNUSED_CLAIM 0x7fffffff

/* ---------------- device scratch (no allocations allowed) ---------------- */
__device__ int  g_counts  [TOTBUK];
__device__ int  g_start   [TOTBUK];
__device__ int  g_cursor  [TOTBUK];
__device__ int  g_order   [V_TOT];
__device__ int  g_selLocal[V_TOT];
__device__ int  g_assign  [V_TOT];
__device__ int  g_segCount[NSEG];
__device__ unsigned char g_used[V_TOT];

__device__ __forceinline__ float clip01(float x) { return fminf(fmaxf(x, 0.f), 1.f); }

__device__ __forceinline__ int bucket_of(float sc) {
    int b = (int)(sc * (float)NBUK);
    b = min(b, NBUK - 1);
    return (NBUK - 1) - b;            /* descending score -> ascending bucket */
}

/* ---- init: fill dirn/sel/backgather with -1.0f, reset scratch ---- */
__global__ void k_init(float4* out4, long n4) {
    long i = (long)blockIdx.x * blockDim.x + threadIdx.x;
    long stride = (long)gridDim.x * blockDim.x;
    float4 m1 = make_float4(-1.f, -1.f, -1.f, -1.f);
    for (long j = i; j < n4; j += stride) out4[j] = m1;
    for (long j = i; j < TOTBUK; j += stride) g_counts[j] = 0;
    for (long j = i; j < V_TOT;  j += stride) g_assign[j] = -1;
}

/* ---- bucket histogram ---- */
__global__ void k_count(const float* __restrict__ score) {
    int v = blockIdx.x * blockDim.x + threadIdx.x;
    if (v >= V_TOT) return;
    int s  = v / SEGLEN;
    int bd = bucket_of(clip01(score[v]));
    atomicAdd(&g_counts[s * NBUK + bd], 1);
}

/* ---- exclusive scan over all buckets (Hillis-Steele over 1024 partials) ---- */
__global__ void k_scan() {
    __shared__ int part[1024];
    const int tid   = threadIdx.x;
    const int chunk = TOTBUK / 1024;    /* 128 */
    const int base  = tid * chunk;
    int ssum = 0;
    for (int j = 0; j < chunk; j++) ssum += g_counts[base + j];
    part[tid] = ssum;
    __syncthreads();
    for (int off = 1; off < 1024; off <<= 1) {
        int add = (tid >= off) ? part[tid - off] : 0;
        __syncthreads();
        part[tid] += add;
        __syncthreads();
    }
    int run = part[tid] - ssum;         /* exclusive */
    for (int j = 0; j < chunk; j++) {
        int c = g_counts[base + j];
        g_start [base + j] = run;
        g_cursor[base + j] = run;
        run += c;
    }
}

/* ---- scatter into buckets (intra-bucket order fixed by k_bsort) ---- */
__global__ void k_scatter(const float* __restrict__ score) {
    int v = blockIdx.x * blockDim.x + threadIdx.x;
    if (v >= V_TOT) return;
    int s  = v / SEGLEN;
    int bd = bucket_of(clip01(score[v]));
    int pos = atomicAdd(&g_cursor[s * NBUK + bd], 1);
    g_order[pos] = v;
}

/* ---- exact within-bucket insertion sort: score DESC, index ASC ---- */
__global__ void k_bsort(const float* __restrict__ score) {
    int b = blockIdx.x * blockDim.x + threadIdx.x;
    if (b >= TOTBUK) return;
    int st = g_start[b];
    int en = (b + 1 < TOTBUK) ? g_start[b + 1] : V_TOT;
    if (en - st <= 1) return;
    for (int i = st + 1; i < en; i++) {
        int   key = g_order[i];
        float ks  = clip01(__ldg(&score[key]));
        int j = i - 1;
        while (j >= st) {
            int   oj = g_order[j];
            float os = clip01(__ldg(&score[oj]));
            bool shift = (os < ks) || (os == ks && oj > key);
            if (!shift) break;
            g_order[j + 1] = oj;
            j--;
        }
        g_order[j + 1] = key;
    }
}

/* ======== PHASE A: batch-speculative greedy over prefix (score >= 0.5) ====
   One 1024-thread CTA per segment. Each batch: collect next 32 unused
   vertices in order (1 warp per candidate), exact within-batch conflict
   cascade, claim neighbours via SMEM atomicMin(rank) (min-rank == earliest
   seed == sequential semantics; claim also serves as the used flag). */
__global__ void __launch_bounds__(1024, 1)
k_batch(const float* __restrict__ score, const int* __restrict__ nidxs,
        float* __restrict__ out)
{
    extern __shared__ int smem_dyn[];
    int*            claim = smem_dyn;                                /* SEGLEN ints  */
    unsigned short* sordu = (unsigned short*)(claim + SEGLEN);       /* SEGLEN u16   */
    int*            ctrl  = (int*)(sordu + SEGLEN);
    int*      candV    = ctrl;            /* [32]  candidate local ids        */
    unsigned* conflict = (unsigned*)(ctrl + 32);  /* [32] within-batch masks  */
    int*      warpTot  = ctrl + 64;       /* [32]  block prefix scratch       */
    int*      S        = ctrl + 96;       /* scalars: 0=need 1=p 2=cut 3=wtot
                                                      4=validMask 5=segCount 6=R0 */

    const int s    = blockIdx.x;
    const int tid  = threadIdx.x;
    const int lane = tid & 31;
    const int wid  = tid >> 5;
    const int segBase = s * SEGLEN;
    const int M = g_start[s * NBUK + HALFBUK] - g_start[s * NBUK];

    for (int i = tid; i < SEGLEN; i += 1024) {
        claim[i] = UNUSED_CLAIM;
        sordu[i] = (unsigned short)(g_order[segBase + i] - segBase);
    }
    if (tid == 0) { S[0] = 0; S[1] = 0; S[5] = 0; S[6] = 0; }
    __syncthreads();

    for (;;) {
        /* ---- collection: next up-to-32 unused vertices in visit order ---- */
        while (S[0] < 32 && S[1] < M) {
            int p    = S[1];
            int need = S[0];
            int idx  = p + tid;
            int vl   = (idx < M) ? (int)sordu[idx] : 0;
            bool flag = (idx < M) && (claim[vl] == UNUSED_CLAIM);
            unsigned bal = __ballot_sync(0xffffffffu, flag);
            int myoff = __popc(bal & ((1u << lane) - 1u));
            if (lane == 0) warpTot[wid] = __popc(bal);
            __syncthreads();
            if (wid == 0) {                       /* exclusive scan of 32 warp totals */
                int v0  = warpTot[lane];
                int pre = v0;
#pragma unroll
                for (int o = 1; o < 32; o <<= 1) {
                    int t = __shfl_up_sync(0xffffffffu, pre, o);
                    if (lane >= o) pre += t;
                }
                warpTot[lane] = pre - v0;
                if (lane == 31) S[3] = pre;       /* window total */
            }
            __syncthreads();
            int rank = need + warpTot[wid] + myoff;
            if (flag && rank < 32)  candV[rank] = vl;
            if (flag && rank == 31) S[2] = idx + 1;
            __syncthreads();
            if (tid == 0) {
                int total = need + S[3];
                if (total >= 32) { S[0] = 32;    S[1] = S[2]; }
                else             { S[0] = total; S[1] = p + 1024; }
            }
            __syncthreads();
        }
        const int B = S[0];
        if (B == 0) break;
        if (tid < 32 && tid >= B) candV[tid] = -2;
        __syncthreads();

        /* ---- per-warp candidate load + within-batch conflict mask ---- */
        int v = -2, gv = 0, c0 = -1, c1 = -1;
        if (wid < B) {
            v  = candV[wid];
            gv = segBase + v;
            float sc = clip01(__ldg(score + gv));
            bool expand = sc > THR;
            if (expand) {
                c0 = __ldg(nidxs + (size_t)gv * K_NB + lane)      - segBase;
                c1 = __ldg(nidxs + (size_t)gv * K_NB + 32 + lane) - segBase;
            } else {
                c0 = (lane == 0) ? v : -1;
                c1 = -1;
            }
            unsigned m = 0;
#pragma unroll
            for (int r = 0; r < 32; r++) {
                int cv = candV[r];
                m |= ((c0 == cv) || (c1 == cv)) ? (1u << r) : 0u;
            }
            m = __reduce_or_sync(0xffffffffu, m);
            if (lane == 0) conflict[wid] = m;
        }
        __syncthreads();

        /* ---- sequential validity cascade (exact order semantics) ---- */
        if (tid == 0) {
            unsigned accum = 0, vmask = 0;
            for (int r = 0; r < B; r++) {
                if (!((accum >> r) & 1u)) { vmask |= 1u << r; accum |= conflict[r]; }
            }
            S[4] = (int)vmask;
        }
        __syncthreads();

        const unsigned vmask    = (unsigned)S[4];
        const int      R0       = S[6];
        const int      segCount = S[5];
        const bool validW = (wid < B) && ((vmask >> wid) & 1u);

        /* ---- claims: earliest (min-rank) valid seed wins each vertex ---- */
        if (validW) {
            if (c0 >= 0) atomicMin(&claim[c0], R0 + wid);
            if (c1 >= 0) atomicMin(&claim[c1], R0 + wid);
        }
        __syncthreads();

        /* ---- grant + output writes ---- */
        if (validW) {
            int cnt = segCount + __popc(vmask & ((1u << wid) - 1u));
            if (c0 >= 0 && claim[c0] == R0 + wid) {
                out[(size_t)gv * K_NB + lane] = (float)(segBase + c0);
                g_assign[segBase + c0] = cnt;
            }
            if (c1 >= 0 && claim[c1] == R0 + wid) {
                out[(size_t)gv * K_NB + 32 + lane] = (float)(segBase + c1);
                g_assign[segBase + c1] = cnt;
            }
            if (lane == 0) g_selLocal[segBase + cnt] = gv;
        }
        __syncthreads();
        if (tid == 0) { S[5] = segCount + __popc(vmask); S[6] = R0 + B; S[0] = 0; }
        __syncthreads();
    }

    if (tid == 0) g_segCount[s] = S[5];
    /* dump used flags for phase B */
    for (int i = tid; i < SEGLEN; i += 1024)
        g_used[segBase + i] = (claim[i] != UNUSED_CLAIM) ? 1 : 0;
}

/* ======== PHASE B: parallel singleton pass over suffix (score < 0.5) ==== */
__global__ void __launch_bounds__(1024)
k_suffix(float* __restrict__ out)
{
    __shared__ int part[1024];
    const int s    = blockIdx.x;
    const int tid  = threadIdx.x;
    const int base = s * SEGLEN;
    const int M      = g_start[s * NBUK + HALFBUK] - base;
    const int countA = g_segCount[s];

    const int N  = SEGLEN - M;
    const int C  = (N + 1023) >> 10;
    const int st = M + tid * C;
    const int en = min(st + C, SEGLEN);

    int cnt = 0;
    for (int i = st; i < en; i++) {
        int v = g_order[base + i];
        cnt += (g_used[v] == 0);
    }
    part[tid] = cnt;
    __syncthreads();
    for (int off = 1; off < 1024; off <<= 1) {
        int add = (tid >= off) ? part[tid - off] : 0;
        __syncthreads();
        part[tid] += add;
        __syncthreads();
    }
    int total = part[1023];
    int rank  = countA + part[tid] - cnt;     /* exclusive */

    for (int i = st; i < en; i++) {
        int v = g_order[base + i];
        if (g_used[v] == 0) {
            out[(size_t)v * K_NB] = (float)v;   /* dirn col 0 = self */
            g_assign[v] = rank;
            g_selLocal[base + rank] = v;
            rank++;
        }
    }
    if (tid == 0) g_segCount[s] = countA + total;
}

/* ---- fixup: global seed-index offsets, sel compaction, rs_new, n_sel ---- */
__global__ void k_fixup(float* __restrict__ out) {
    int c0 = g_segCount[0], c1 = g_segCount[1],
        c2 = g_segCount[2], c3 = g_segCount[3];
    int off1 = c0, off2 = c0 + c1, off3 = c0 + c1 + c2;
    int total = off3 + c3;

    float* sel    = out + (size_t)V_TOT * K_NB;   /* (V,1)  */
    float* assign = sel + V_TOT;                  /* (V,)   */
    float* rs     = assign + V_TOT;               /* (5,)+1 */

    int t      = blockIdx.x * blockDim.x + threadIdx.x;
    int stride = gridDim.x * blockDim.x;

    for (int v = t; v < V_TOT; v += stride) {
        int s = v / SEGLEN;
        int off = (s == 0) ? 0    : (s == 1) ? off1 : (s == 2) ? off2 : off3;
        int cnt = (s == 0) ? c0   : (s == 1) ? c1   : (s == 2) ? c2   : c3;
        int a = g_assign[v];
        if (a >= 0) assign[v] = (float)(a + off);
        int j = v - s * SEGLEN;
        if (j < cnt) sel[off + j] = (float)g_selLocal[v];
    }
    if (t == 0) {
        rs[0] = 0.f;  rs[1] = (float)off1; rs[2] = (float)off2;
        rs[3] = (float)off3; rs[4] = (float)total;
        rs[5] = (float)total;             /* n_sel */
    }
}

/* ------------------------------------------------------------------------ */
extern "C" void kernel_launch(void* const* d_in, const int* in_sizes, int n_in,
                              void* d_out, int out_size)
{
    const float* score = (const float*)d_in[0];
    const int*   nidxs = (const int*)  d_in[1];
    float* out = (float*)d_out;

    const long nfill  = (long)V_TOT * K_NB + 2L * V_TOT;
    const long nfill4 = nfill / 4;

    /* claim (128KB) + sordu (64KB) + ctrl (512B) */
    const int dynBytes = SEGLEN * sizeof(int) + SEGLEN * sizeof(unsigned short) + 512;
    cudaFuncSetAttribute(k_batch,
                         cudaFuncAttributeMaxDynamicSharedMemorySize, dynBytes);

    k_init   <<<2048, 256>>>((float4*)out, nfill4);
    k_count  <<<V_TOT / 256, 256>>>(score);
    k_scan   <<<1, 1024>>>();
    k_scatter<<<V_TOT / 256, 256>>>(score);
    k_bsort  <<<TOTBUK / 256, 256>>>(score);
    k_batch  <<<NSEG, 1024, dynBytes>>>(score, nidxs, out);
    k_suffix <<<NSEG, 1024>>>(out);
    k_fixup  <<<256, 256>>>(out);
}

// round 8
// speedup vs baseline: 2.7813x; 1.4090x over previous
#include <cuda_runtime.h>

#define V_TOT   131072
#define K_NB    64
#define NSEG    4
#define SEGLEN  (V_TOT / NSEG)     /* 32768 */
#define NBUK    SEGLEN
#define THR     0.5f
#define HALFBUK 16384              /* buckets [0,HALFBUK) <=> score >= 0.5 */
#define BATCH   64
#define UNUSED_CLAIM 0x7fffffff

/* ---------------- device scratch (no allocations allowed) ---------------- */
__device__ int  g_order   [V_TOT];
__device__ int  g_selLocal[V_TOT];
__device__ int  g_assign  [V_TOT];
__device__ int  g_segCount[NSEG];
__device__ int  g_M       [NSEG];
__device__ unsigned char g_used[V_TOT];

__device__ __forceinline__ float clip01(float x) { return fminf(fmaxf(x, 0.f), 1.f); }

__device__ __forceinline__ int bucket_of(float sc) {
    int b = (int)(sc * (float)NBUK);
    b = min(b, NBUK - 1);
    return (NBUK - 1) - b;            /* descending score -> ascending bucket */
}

/* ---- init: fill dirn/sel/backgather with -1.0f, reset g_assign ---- */
__global__ void k_init(float4* out4, long n4) {
    long i = (long)blockIdx.x * blockDim.x + threadIdx.x;
    long stride = (long)gridDim.x * blockDim.x;
    float4 m1 = make_float4(-1.f, -1.f, -1.f, -1.f);
    for (long j = i; j < n4; j += stride) out4[j] = m1;
    for (long j = i; j < V_TOT; j += stride) g_assign[j] = -1;
}

/* ---- fused per-segment sort: histogram+scan+scatter+bucket-sort in SMEM.
   One 1024-thread CTA per segment; no cross-CTA deps. Exact lexsort order:
   score DESC, index ASC. ---- */
__global__ void __launch_bounds__(1024, 1)
k_sort(const float* __restrict__ score)
{
    extern __shared__ int smem[];
    int* cnt  = smem;            /* NBUK ints   */
    int* part = smem + NBUK;     /* 1024 ints   */

    const int s   = blockIdx.x;
    const int tid = threadIdx.x;
    const int segBase = s * SEGLEN;

    for (int i = tid; i < NBUK; i += 1024) cnt[i] = 0;
    __syncthreads();

    for (int i = tid; i < SEGLEN; i += 1024) {
        int b = bucket_of(clip01(__ldg(score + segBase + i)));
        atomicAdd(&cnt[b], 1);
    }
    __syncthreads();

    /* exclusive scan over NBUK: 32-chunk per thread + Hillis-Steele on 1024 */
    const int chunk = NBUK / 1024;   /* 32 */
    const int base  = tid * chunk;
    int ssum = 0;
    for (int j = 0; j < chunk; j++) ssum += cnt[base + j];
    part[tid] = ssum;
    __syncthreads();
    for (int off = 1; off < 1024; off <<= 1) {
        int add = (tid >= off) ? part[tid - off] : 0;
        __syncthreads();
        part[tid] += add;
        __syncthreads();
    }
    int run = part[tid] - ssum;
    for (int j = 0; j < chunk; j++) {
        int c = cnt[base + j];
        cnt[base + j] = run;          /* starts */
        run += c;
    }
    __syncthreads();
    if (tid == 0) g_M[s] = cnt[HALFBUK];   /* # vertices with score >= 0.5 */
    __syncthreads();

    /* scatter (intra-bucket order fixed below) */
    for (int i = tid; i < SEGLEN; i += 1024) {
        int b = bucket_of(clip01(__ldg(score + segBase + i)));
        int pos = atomicAdd(&cnt[b], 1);
        g_order[segBase + pos] = segBase + i;
    }
    __syncthreads();

    /* exact within-bucket insertion sort (cnt[b] now = end of bucket b) */
    for (int b = tid; b < NBUK; b += 1024) {
        int st = (b == 0) ? 0 : cnt[b - 1];
        int en = cnt[b];
        for (int i = st + 1; i < en; i++) {
            int   key = g_order[segBase + i];
            float ks  = clip01(__ldg(score + key));
            int j = i - 1;
            while (j >= st) {
                int   oj = g_order[segBase + j];
                float os = clip01(__ldg(score + oj));
                bool shift = (os < ks) || (os == ks && oj > key);
                if (!shift) break;
                g_order[segBase + j + 1] = oj;
                j--;
            }
            g_order[segBase + j + 1] = key;
        }
    }
}

/* no-op pad so k_batch lands in ncu's fixed capture slot (my 4th launch) */
__global__ void k_pad() {}

/* ======== PHASE A: batch-speculative greedy, B=64 per batch ========
   One 1024-thread CTA per segment; 2 candidates per warp. Exact
   within-batch conflict cascade (64-bit) + min-rank SMEM claims. */
__global__ void __launch_bounds__(1024, 1)
k_batch(const float* __restrict__ score, const int* __restrict__ nidxs,
        float* __restrict__ out)
{
    extern __shared__ int smem_dyn[];
    int*            claim = smem_dyn;                           /* SEGLEN ints */
    unsigned short* sordu = (unsigned short*)(claim + SEGLEN);  /* SEGLEN u16  */
    int*      ctrl    = (int*)(sordu + SEGLEN);
    int*      candV   = ctrl;                 /* [64]  */
    unsigned* confLo  = (unsigned*)(ctrl + 64);   /* [64] */
    unsigned* confHi  = (unsigned*)(ctrl + 128);  /* [64] */
    int*      warpTot = ctrl + 192;           /* [32]  */
    int*      S       = ctrl + 224;  /* 0=need 1=p 2=cut 3=wtot 4=vmLo 5=vmHi 6=segCount 7=R0 */

    const int s    = blockIdx.x;
    const int tid  = threadIdx.x;
    const int lane = tid & 31;
    const int wid  = tid >> 5;
    const int segBase = s * SEGLEN;
    const int M = g_M[s];

    for (int i = tid; i < SEGLEN; i += 1024) {
        claim[i] = UNUSED_CLAIM;
        sordu[i] = (unsigned short)(g_order[segBase + i] - segBase);
    }
    if (tid == 0) { S[0] = 0; S[1] = 0; S[6] = 0; S[7] = 0; }
    __syncthreads();

    for (;;) {
        /* ---- collection: next up-to-64 unused vertices in visit order ---- */
        while (S[0] < BATCH && S[1] < M) {
            int p    = S[1];
            int need = S[0];
            int idx  = p + tid;
            int vl   = (idx < M) ? (int)sordu[idx] : 0;
            bool flag = (idx < M) && (claim[vl] == UNUSED_CLAIM);
            unsigned bal = __ballot_sync(0xffffffffu, flag);
            int myoff = __popc(bal & ((1u << lane) - 1u));
            if (lane == 0) warpTot[wid] = __popc(bal);
            __syncthreads();
            if (wid == 0) {
                int v0  = warpTot[lane];
                int pre = v0;
#pragma unroll
                for (int o = 1; o < 32; o <<= 1) {
                    int t = __shfl_up_sync(0xffffffffu, pre, o);
                    if (lane >= o) pre += t;
                }
                warpTot[lane] = pre - v0;
                if (lane == 31) S[3] = pre;
            }
            __syncthreads();
            int rank = need + warpTot[wid] + myoff;
            if (flag && rank < BATCH)      candV[rank] = vl;
            if (flag && rank == BATCH - 1) S[2] = idx + 1;
            __syncthreads();
            if (tid == 0) {
                int total = need + S[3];
                if (total >= BATCH) { S[0] = BATCH; S[1] = S[2]; }
                else                { S[0] = total; S[1] = p + 1024; }
            }
            __syncthreads();
        }
        const int B = S[0];
        if (B == 0) break;
        if (tid < BATCH && tid >= B) candV[tid] = -2;
        __syncthreads();

        const int R0   = S[7];
        const int segC = S[6];
        const int j0 = 2 * wid, j1 = 2 * wid + 1;
        const int v0 = candV[j0], v1 = candV[j1];

        /* load both candidates' neighbour rows (local ids, -1 = none) */
        int a00 = -1, a01 = -1, a10 = -1, a11 = -1;
        if (v0 >= 0) {
            int gv = segBase + v0;
            if (__ldg(score + gv) > THR) {
                a00 = __ldg(nidxs + (size_t)gv * K_NB + lane)      - segBase;
                a01 = __ldg(nidxs + (size_t)gv * K_NB + 32 + lane) - segBase;
            } else { a00 = (lane == 0) ? v0 : -1; }
        }
        if (v1 >= 0) {
            int gv = segBase + v1;
            if (__ldg(score + gv) > THR) {
                a10 = __ldg(nidxs + (size_t)gv * K_NB + lane)      - segBase;
                a11 = __ldg(nidxs + (size_t)gv * K_NB + 32 + lane) - segBase;
            } else { a10 = (lane == 0) ? v1 : -1; }
        }

        /* within-batch conflict masks (64-bit per candidate) */
        unsigned m0lo = 0, m0hi = 0, m1lo = 0, m1hi = 0;
#pragma unroll 8
        for (int r = 0; r < 32; r++) {
            int cv = candV[r];
            m0lo |= ((a00 == cv) | (a01 == cv)) ? (1u << r) : 0u;
            m1lo |= ((a10 == cv) | (a11 == cv)) ? (1u << r) : 0u;
        }
#pragma unroll 8
        for (int r = 0; r < 32; r++) {
            int cv = candV[32 + r];
            m0hi |= ((a00 == cv) | (a01 == cv)) ? (1u << r) : 0u;
            m1hi |= ((a10 == cv) | (a11 == cv)) ? (1u << r) : 0u;
        }
        m0lo = __reduce_or_sync(0xffffffffu, m0lo);
        m0hi = __reduce_or_sync(0xffffffffu, m0hi);
        m1lo = __reduce_or_sync(0xffffffffu, m1lo);
        m1hi = __reduce_or_sync(0xffffffffu, m1hi);
        if (lane == 0) {
            confLo[j0] = m0lo; confHi[j0] = m0hi;
            confLo[j1] = m1lo; confHi[j1] = m1hi;
        }
        __syncthreads();

        /* sequential validity cascade (exact order semantics) */
        if (tid == 0) {
            unsigned long long accum = 0, vm = 0;
            for (int r = 0; r < B; r++) {
                if (!((accum >> r) & 1ull)) {
                    vm    |= 1ull << r;
                    accum |= ((unsigned long long)confHi[r] << 32) | confLo[r];
                }
            }
            S[4] = (int)(vm & 0xffffffffull);
            S[5] = (int)(vm >> 32);
        }
        __syncthreads();

        const unsigned long long vmask =
            ((unsigned long long)(unsigned)S[5] << 32) | (unsigned)S[4];
        const bool val0 = (j0 < B) && ((vmask >> j0) & 1ull);
        const bool val1 = (j1 < B) && ((vmask >> j1) & 1ull);

        /* claims: earliest (min-rank) valid seed wins each vertex */
        if (val0) {
            if (a00 >= 0) atomicMin(&claim[a00], R0 + j0);
            if (a01 >= 0) atomicMin(&claim[a01], R0 + j0);
        }
        if (val1) {
            if (a10 >= 0) atomicMin(&claim[a10], R0 + j1);
            if (a11 >= 0) atomicMin(&claim[a11], R0 + j1);
        }
        __syncthreads();

        /* grants + output writes */
        if (val0) {
            int cnt = segC + __popcll(vmask & ((1ull << j0) - 1ull));
            int gv  = segBase + v0;
            if (a00 >= 0 && claim[a00] == R0 + j0) {
                out[(size_t)gv * K_NB + lane] = (float)(segBase + a00);
                g_assign[segBase + a00] = cnt;
            }
            if (a01 >= 0 && claim[a01] == R0 + j0) {
                out[(size_t)gv * K_NB + 32 + lane] = (float)(segBase + a01);
                g_assign[segBase + a01] = cnt;
            }
            if (lane == 0) g_selLocal[segBase + cnt] = gv;
        }
        if (val1) {
            int cnt = segC + __popcll(vmask & ((1ull << j1) - 1ull));
            int gv  = segBase + v1;
            if (a10 >= 0 && claim[a10] == R0 + j1) {
                out[(size_t)gv * K_NB + lane] = (float)(segBase + a10);
                g_assign[segBase + a10] = cnt;
            }
            if (a11 >= 0 && claim[a11] == R0 + j1) {
                out[(size_t)gv * K_NB + 32 + lane] = (float)(segBase + a11);
                g_assign[segBase + a11] = cnt;
            }
            if (lane == 0) g_selLocal[segBase + cnt] = gv;
        }
        __syncthreads();
        if (tid == 0) {
            S[6] = segC + __popcll(vmask);
            S[7] = R0 + B;
            S[0] = 0;
        }
        __syncthreads();
    }

    if (tid == 0) g_segCount[s] = S[6];
    for (int i = tid; i < SEGLEN; i += 1024)
        g_used[segBase + i] = (claim[i] != UNUSED_CLAIM) ? 1 : 0;
}

/* ======== PHASE B: parallel singleton pass over suffix (score < 0.5) ==== */
__global__ void __launch_bounds__(1024)
k_suffix(float* __restrict__ out)
{
    __shared__ int part[1024];
    const int s    = blockIdx.x;
    const int tid  = threadIdx.x;
    const int base = s * SEGLEN;
    const int M      = g_M[s];
    const int countA = g_segCount[s];

    const int N  = SEGLEN - M;
    const int C  = (N + 1023) >> 10;
    const int st = M + tid * C;
    const int en = min(st + C, SEGLEN);

    int cnt = 0;
    for (int i = st; i < en; i++) {
        int v = g_order[base + i];
        cnt += (g_used[v] == 0);
    }
    part[tid] = cnt;
    __syncthreads();
    for (int off = 1; off < 1024; off <<= 1) {
        int add = (tid >= off) ? part[tid - off] : 0;
        __syncthreads();
        part[tid] += add;
        __syncthreads();
    }
    int total = part[1023];
    int rank  = countA + part[tid] - cnt;

    for (int i = st; i < en; i++) {
        int v = g_order[base + i];
        if (g_used[v] == 0) {
            out[(size_t)v * K_NB] = (float)v;
            g_assign[v] = rank;
            g_selLocal[base + rank] = v;
            rank++;
        }
    }
    if (tid == 0) g_segCount[s] = countA + total;
}

/* ---- fixup: global seed-index offsets, sel compaction, rs_new, n_sel ---- */
__global__ void k_fixup(float* __restrict__ out) {
    int c0 = g_segCount[0], c1 = g_segCount[1],
        c2 = g_segCount[2], c3 = g_segCount[3];
    int off1 = c0, off2 = c0 + c1, off3 = c0 + c1 + c2;
    int total = off3 + c3;

    float* sel    = out + (size_t)V_TOT * K_NB;
    float* assign = sel + V_TOT;
    float* rs     = assign + V_TOT;

    int t      = blockIdx.x * blockDim.x + threadIdx.x;
    int stride = gridDim.x * blockDim.x;

    for (int v = t; v < V_TOT; v += stride) {
        int s = v / SEGLEN;
        int off = (s == 0) ? 0  : (s == 1) ? off1 : (s == 2) ? off2 : off3;
        int cnt = (s == 0) ? c0 : (s == 1) ? c1   : (s == 2) ? c2   : c3;
        int a = g_assign[v];
        if (a >= 0) assign[v] = (float)(a + off);
        int j = v - s * SEGLEN;
        if (j < cnt) sel[off + j] = (float)g_selLocal[v];
    }
    if (t == 0) {
        rs[0] = 0.f;  rs[1] = (float)off1; rs[2] = (float)off2;
        rs[3] = (float)off3; rs[4] = (float)total;
        rs[5] = (float)total;
    }
}

/* ------------------------------------------------------------------------ */
extern "C" void kernel_launch(void* const* d_in, const int* in_sizes, int n_in,
                              void* d_out, int out_size)
{
    const float* score = (const float*)d_in[0];
    const int*   nidxs = (const int*)  d_in[1];
    float* out = (float*)d_out;

    const long nfill  = (long)V_TOT * K_NB + 2L * V_TOT;
    const long nfill4 = nfill / 4;

    const int sortBytes  = NBUK * sizeof(int) + 1024 * sizeof(int);       /* 132KB */
    const int batchBytes = SEGLEN * sizeof(int) + SEGLEN * sizeof(unsigned short) + 1024;
    cudaFuncSetAttribute(k_sort,
                         cudaFuncAttributeMaxDynamicSharedMemorySize, sortBytes);
    cudaFuncSetAttribute(k_batch,
                         cudaFuncAttributeMaxDynamicSharedMemorySize, batchBytes);

    k_init  <<<2048, 256>>>((float4*)out, nfill4);
    k_sort  <<<NSEG, 1024, sortBytes>>>(score);
    k_pad   <<<1, 32>>>();
    k_batch <<<NSEG, 1024, batchBytes>>>(score, nidxs, out);   /* profiled slot */
    k_suffix<<<NSEG, 1024>>>(out);
    k_fixup <<<256, 256>>>(out);
}

// round 9
// speedup vs baseline: 4.9563x; 1.7820x over previous
#include <cuda_runtime.h>

#define V_TOT   131072
#define K_NB    64
#define NSEG    4
#define SEGLEN  (V_TOT / NSEG)     /* 32768 */
#define NBUK    SEGLEN
#define THR     0.5f
#define HALFBUK 16384
#define BATCH   64
#define UNUSED_CLAIM 0x7fffffff
#define CAND_BASE    0x40000000

/* ---------------- device scratch (no allocations allowed) ---------------- */
__device__ int  g_order   [V_TOT];
__device__ int  g_selLocal[V_TOT];
__device__ int  g_assign  [V_TOT];
__device__ int  g_segCount[NSEG];
__device__ int  g_M       [NSEG];

__device__ __forceinline__ float clip01(float x) { return fminf(fmaxf(x, 0.f), 1.f); }

__device__ __forceinline__ int bucket_of(float sc) {
    int b = (int)(sc * (float)NBUK);
    b = min(b, NBUK - 1);
    return (NBUK - 1) - b;
}

/* ---- init: fill dirn/sel/backgather with -1.0f, reset g_assign ---- */
__global__ void k_init(float4* out4, long n4) {
    long i = (long)blockIdx.x * blockDim.x + threadIdx.x;
    long stride = (long)gridDim.x * blockDim.x;
    float4 m1 = make_float4(-1.f, -1.f, -1.f, -1.f);
    for (long j = i; j < n4; j += stride) out4[j] = m1;
    for (long j = i; j < V_TOT; j += stride) g_assign[j] = -1;
}

/* ---- fused per-segment sort: histogram+scan+scatter+bucket-sort ---- */
__global__ void __launch_bounds__(1024, 1)
k_sort(const float* __restrict__ score)
{
    extern __shared__ int smem[];
    int* cnt  = smem;            /* NBUK ints */
    int* part = smem + NBUK;     /* 1024 ints */

    const int s   = blockIdx.x;
    const int tid = threadIdx.x;
    const int segBase = s * SEGLEN;

    for (int i = tid; i < NBUK; i += 1024) cnt[i] = 0;
    __syncthreads();

    for (int i = tid; i < SEGLEN; i += 1024) {
        int b = bucket_of(clip01(__ldg(score + segBase + i)));
        atomicAdd(&cnt[b], 1);
    }
    __syncthreads();

    const int chunk = NBUK / 1024;   /* 32 */
    const int base  = tid * chunk;
    int ssum = 0;
    for (int j = 0; j < chunk; j++) ssum += cnt[base + j];
    part[tid] = ssum;
    __syncthreads();
    for (int off = 1; off < 1024; off <<= 1) {
        int add = (tid >= off) ? part[tid - off] : 0;
        __syncthreads();
        part[tid] += add;
        __syncthreads();
    }
    int run = part[tid] - ssum;
    for (int j = 0; j < chunk; j++) {
        int c = cnt[base + j];
        cnt[base + j] = run;
        run += c;
    }
    __syncthreads();
    if (tid == 0) g_M[s] = cnt[HALFBUK];
    __syncthreads();

    for (int i = tid; i < SEGLEN; i += 1024) {
        int b = bucket_of(clip01(__ldg(score + segBase + i)));
        int pos = atomicAdd(&cnt[b], 1);
        g_order[segBase + pos] = segBase + i;
    }
    __syncthreads();

    for (int b = tid; b < NBUK; b += 1024) {
        int st = (b == 0) ? 0 : cnt[b - 1];
        int en = cnt[b];
        for (int i = st + 1; i < en; i++) {
            int   key = g_order[segBase + i];
            float ks  = clip01(__ldg(score + key));
            int j = i - 1;
            while (j >= st) {
                int   oj = g_order[segBase + j];
                float os = clip01(__ldg(score + oj));
                bool shift = (os < ks) || (os == ks && oj > key);
                if (!shift) break;
                g_order[segBase + j + 1] = oj;
                j--;
            }
            g_order[segBase + j + 1] = key;
        }
    }
}

/* keep k_batch in ncu's fixed capture slot (4th launch) */
__global__ void k_pad() {}

/* ======== batch-speculative greedy (B=64) + fused suffix pass ========
   Conflict detection is O(1) per neighbour via claim-encoding: candidates
   carry claim = CAND_BASE + rank during the batch; every candidate ends
   the batch with a real rank (self-claim when valid, absorber's claim
   when invalidated), so no reset is required. Cascade only walks the ~7
   non-zero conflict masks per batch. */
__global__ void __launch_bounds__(1024, 1)
k_batch(const float* __restrict__ score, const int* __restrict__ nidxs,
        float* __restrict__ out)
{
    extern __shared__ int smem_dyn[];
    int*                 claim = smem_dyn;                             /* SEGLEN */
    unsigned short*      sordu = (unsigned short*)(claim + SEGLEN);    /* SEGLEN */
    int*                 part  = (int*)(sordu + SEGLEN);               /* 1024   */
    unsigned long long*  conf  = (unsigned long long*)(part + 1024);   /* 64     */
    int*  ctrl    = (int*)(conf + 64);
    int*  candV   = ctrl;        /* [64] */
    int*  warpTot = ctrl + 64;   /* [32] */
    int*  S       = ctrl + 96;   /* 0=need 1=p 2=cut 3=wtot 4=vmLo 5=vmHi
                                    6=segCount 7=R0 8=evLo 9=evHi */

    const int s    = blockIdx.x;
    const int tid  = threadIdx.x;
    const int lane = tid & 31;
    const int wid  = tid >> 5;
    const int segBase = s * SEGLEN;
    const int M = g_M[s];

    for (int i = tid; i < SEGLEN; i += 1024) {
        claim[i] = UNUSED_CLAIM;
        sordu[i] = (unsigned short)(g_order[segBase + i] - segBase);
    }
    if (tid == 0) { S[0] = 0; S[1] = 0; S[6] = 0; S[7] = 0; }
    __syncthreads();

    for (;;) {
        /* ---- collect next up-to-64 unused vertices in visit order ---- */
        while (S[0] < BATCH && S[1] < M) {
            int p    = S[1];
            int need = S[0];
            int idx  = p + tid;
            int vl   = (idx < M) ? (int)sordu[idx] : 0;
            bool flag = (idx < M) && (claim[vl] == UNUSED_CLAIM);
            unsigned bal = __ballot_sync(0xffffffffu, flag);
            int myoff = __popc(bal & ((1u << lane) - 1u));
            if (lane == 0) warpTot[wid] = __popc(bal);
            __syncthreads();
            if (wid == 0) {
                int v0  = warpTot[lane];
                int pre = v0;
#pragma unroll
                for (int o = 1; o < 32; o <<= 1) {
                    int t = __shfl_up_sync(0xffffffffu, pre, o);
                    if (lane >= o) pre += t;
                }
                warpTot[lane] = pre - v0;
                if (lane == 31) S[3] = pre;
            }
            __syncthreads();
            int rank = need + warpTot[wid] + myoff;
            if (flag && rank < BATCH)      candV[rank] = vl;
            if (flag && rank == BATCH - 1) S[2] = idx + 1;
            __syncthreads();
            if (tid == 0) {
                int total = need + S[3];
                if (total >= BATCH) { S[0] = BATCH; S[1] = S[2]; }
                else                { S[0] = total; S[1] = p + 1024; }
            }
            __syncthreads();
        }
        const int B = S[0];
        if (B == 0) break;
        /* mark candidates in claim; pad unused slots */
        if (tid < BATCH) {
            if (tid >= B) candV[tid] = -2;
            else          claim[candV[tid]] = CAND_BASE + tid;
        }
        __syncthreads();

        const int R0   = S[7];
        const int segC = S[6];
        const int j0 = 2 * wid, j1 = 2 * wid + 1;
        const int v0 = candV[j0], v1 = candV[j1];

        int a00 = -1, a01 = -1, a10 = -1, a11 = -1;
        if (v0 >= 0) {
            int gv = segBase + v0;
            if (__ldg(score + gv) > THR) {
                a00 = __ldg(nidxs + (size_t)gv * K_NB + lane)      - segBase;
                a01 = __ldg(nidxs + (size_t)gv * K_NB + 32 + lane) - segBase;
            } else { a00 = (lane == 0) ? v0 : -1; }
        }
        if (v1 >= 0) {
            int gv = segBase + v1;
            if (__ldg(score + gv) > THR) {
                a10 = __ldg(nidxs + (size_t)gv * K_NB + lane)      - segBase;
                a11 = __ldg(nidxs + (size_t)gv * K_NB + 32 + lane) - segBase;
            } else { a10 = (lane == 0) ? v1 : -1; }
        }

        /* O(1) conflict lookup per neighbour via claim encoding */
        unsigned long long m0 = 0, m1 = 0;
        {
            int c;
            c = (a00 >= 0) ? claim[a00] : 0;
            if ((unsigned)(c - CAND_BASE) < 64u) m0 |= 1ull << (c - CAND_BASE);
            c = (a01 >= 0) ? claim[a01] : 0;
            if ((unsigned)(c - CAND_BASE) < 64u) m0 |= 1ull << (c - CAND_BASE);
            c = (a10 >= 0) ? claim[a10] : 0;
            if ((unsigned)(c - CAND_BASE) < 64u) m1 |= 1ull << (c - CAND_BASE);
            c = (a11 >= 0) ? claim[a11] : 0;
            if ((unsigned)(c - CAND_BASE) < 64u) m1 |= 1ull << (c - CAND_BASE);
        }
        unsigned m0lo = __reduce_or_sync(0xffffffffu, (unsigned)m0);
        unsigned m0hi = __reduce_or_sync(0xffffffffu, (unsigned)(m0 >> 32));
        unsigned m1lo = __reduce_or_sync(0xffffffffu, (unsigned)m1);
        unsigned m1hi = __reduce_or_sync(0xffffffffu, (unsigned)(m1 >> 32));
        if (lane == 0) {
            /* clear self bits so zero-mask <=> no cross-candidate conflict */
            conf[j0] = (((unsigned long long)m0hi << 32) | m0lo) & ~(1ull << j0);
            conf[j1] = (((unsigned long long)m1hi << 32) | m1lo) & ~(1ull << j1);
        }
        __syncthreads();

        /* event mask: which ranks have non-zero conflict masks */
        if (wid < 2) {
            bool nz = conf[wid * 32 + lane] != 0ull;
            unsigned b = __ballot_sync(0xffffffffu, nz);
            if (lane == 0) S[8 + wid] = (int)b;
        }
        __syncthreads();

        /* event-skipping sequential cascade (exact order semantics) */
        if (tid == 0) {
            const unsigned long long Ball =
                (B == 64) ? ~0ull : ((1ull << B) - 1ull);
            unsigned long long events =
                (((unsigned long long)(unsigned)S[9] << 32) | (unsigned)S[8]) & Ball;
            unsigned long long accum = 0, vm = 0, donebits = 0;
            while (events) {
                int e = __ffsll((long long)events) - 1;
                events &= events - 1;
                unsigned long long upto = (e == 63) ? ~0ull : ((1ull << (e + 1)) - 1ull);
                vm |= (upto & ~donebits) & ~accum;
                donebits = upto;
                if ((vm >> e) & 1ull) accum |= conf[e];
            }
            vm |= Ball & ~donebits & ~accum;
            vm &= Ball;
            S[4] = (int)(vm & 0xffffffffull);
            S[5] = (int)(vm >> 32);
        }
        __syncthreads();

        const unsigned long long vmask =
            ((unsigned long long)(unsigned)S[5] << 32) | (unsigned)S[4];
        const bool val0 = (j0 < B) && ((vmask >> j0) & 1ull);
        const bool val1 = (j1 < B) && ((vmask >> j1) & 1ull);

        /* claims: earliest (min-rank) valid seed wins each vertex */
        if (val0) {
            if (a00 >= 0) atomicMin(&claim[a00], R0 + j0);
            if (a01 >= 0) atomicMin(&claim[a01], R0 + j0);
        }
        if (val1) {
            if (a10 >= 0) atomicMin(&claim[a10], R0 + j1);
            if (a11 >= 0) atomicMin(&claim[a11], R0 + j1);
        }
        __syncthreads();

        /* grants + output writes */
        if (val0) {
            int cnt = segC + __popcll(vmask & ((1ull << j0) - 1ull));
            int gv  = segBase + v0;
            if (a00 >= 0 && claim[a00] == R0 + j0) {
                out[(size_t)gv * K_NB + lane] = (float)(segBase + a00);
                g_assign[segBase + a00] = cnt;
            }
            if (a01 >= 0 && claim[a01] == R0 + j0) {
                out[(size_t)gv * K_NB + 32 + lane] = (float)(segBase + a01);
                g_assign[segBase + a01] = cnt;
            }
            if (lane == 0) g_selLocal[segBase + cnt] = gv;
        }
        if (val1) {
            int cnt = segC + __popcll(vmask & ((1ull << j1) - 1ull));
            int gv  = segBase + v1;
            if (a10 >= 0 && claim[a10] == R0 + j1) {
                out[(size_t)gv * K_NB + lane] = (float)(segBase + a10);
                g_assign[segBase + a10] = cnt;
            }
            if (a11 >= 0 && claim[a11] == R0 + j1) {
                out[(size_t)gv * K_NB + 32 + lane] = (float)(segBase + a11);
                g_assign[segBase + a11] = cnt;
            }
            if (lane == 0) g_selLocal[segBase + cnt] = gv;
        }
        __syncthreads();
        if (tid == 0) {
            S[6] = segC + __popcll(vmask);
            S[7] = R0 + B;
            S[0] = 0;
        }
        __syncthreads();
    }

    /* ======== fused suffix pass: singletons over score < 0.5 ======== */
    const int countA = S[6];
    const int N  = SEGLEN - M;
    const int C  = (N + 1023) >> 10;
    const int st = M + tid * C;
    const int en = min(st + C, SEGLEN);

    int cnt = 0;
    for (int i = st; i < en; i++)
        cnt += (claim[sordu[i]] == UNUSED_CLAIM);
    part[tid] = cnt;
    __syncthreads();
    for (int off = 1; off < 1024; off <<= 1) {
        int add = (tid >= off) ? part[tid - off] : 0;
        __syncthreads();
        part[tid] += add;
        __syncthreads();
    }
    int total = part[1023];
    int rank  = countA + part[tid] - cnt;

    for (int i = st; i < en; i++) {
        int v = sordu[i];
        if (claim[v] == UNUSED_CLAIM) {
            int gv = segBase + v;
            out[(size_t)gv * K_NB] = (float)gv;
            g_assign[gv] = rank;
            g_selLocal[segBase + rank] = gv;
            rank++;
        }
    }
    if (tid == 0) g_segCount[s] = countA + total;
}

/* ---- fixup: global seed-index offsets, sel compaction, rs_new, n_sel ---- */
__global__ void k_fixup(float* __restrict__ out) {
    int c0 = g_segCount[0], c1 = g_segCount[1],
        c2 = g_segCount[2], c3 = g_segCount[3];
    int off1 = c0, off2 = c0 + c1, off3 = c0 + c1 + c2;
    int total = off3 + c3;

    float* sel    = out + (size_t)V_TOT * K_NB;
    float* assign = sel + V_TOT;
    float* rs     = assign + V_TOT;

    int t      = blockIdx.x * blockDim.x + threadIdx.x;
    int stride = gridDim.x * blockDim.x;

    for (int v = t; v < V_TOT; v += stride) {
        int s = v / SEGLEN;
        int off = (s == 0) ? 0  : (s == 1) ? off1 : (s == 2) ? off2 : off3;
        int cnt = (s == 0) ? c0 : (s == 1) ? c1   : (s == 2) ? c2   : c3;
        int a = g_assign[v];
        if (a >= 0) assign[v] = (float)(a + off);
        int j = v - s * SEGLEN;
        if (j < cnt) sel[off + j] = (float)g_selLocal[v];
    }
    if (t == 0) {
        rs[0] = 0.f;  rs[1] = (float)off1; rs[2] = (float)off2;
        rs[3] = (float)off3; rs[4] = (float)total;
        rs[5] = (float)total;
    }
}

/* ------------------------------------------------------------------------ */
extern "C" void kernel_launch(void* const* d_in, const int* in_sizes, int n_in,
                              void* d_out, int out_size)
{
    const float* score = (const float*)d_in[0];
    const int*   nidxs = (const int*)  d_in[1];
    float* out = (float*)d_out;

    const long nfill  = (long)V_TOT * K_NB + 2L * V_TOT;
    const long nfill4 = nfill / 4;

    const int sortBytes  = NBUK * sizeof(int) + 1024 * sizeof(int);
    const int batchBytes = SEGLEN * sizeof(int)              /* claim  */
                         + SEGLEN * sizeof(unsigned short)   /* sordu  */
                         + 1024 * sizeof(int)                /* part   */
                         + 64 * sizeof(unsigned long long)   /* conf   */
                         + 128 * sizeof(int);                /* ctrl   */
    cudaFuncSetAttribute(k_sort,
                         cudaFuncAttributeMaxDynamicSharedMemorySize, sortBytes);
    cudaFuncSetAttribute(k_batch,
                         cudaFuncAttributeMaxDynamicSharedMemorySize, batchBytes);

    k_init <<<2048, 256>>>((float4*)out, nfill4);
    k_sort <<<NSEG, 1024, sortBytes>>>(score);
    k_pad  <<<1, 32>>>();
    k_batch<<<NSEG, 1024, batchBytes>>>(score, nidxs, out);   /* profiled slot */
    k_fixup<<<256, 256>>>(out);
}